// round 7
// baseline (speedup 1.0000x reference)
#include <cuda_runtime.h>
#include <cuda_fp16.h>
#include <cstdint>

#define SEQ   512
#define BATCH 4
#define NROWS (BATCH * SEQ)
#define DEMB  768
#define DCAT  784
#define VOCAB 50265
#define NPAD  50432           // 197 N-tiles * 256
#define MSZ   (BATCH * SEQ * SEQ)

__device__ float  g_M1 [MSZ];
__device__ float  g_M2 [MSZ];
__device__ float  g_M3 [MSZ];
__device__ float  g_M4 [MSZ];
__device__ float  g_M8 [MSZ];
__device__ float  g_M12[MSZ];
__device__ float  g_x[NROWS * DCAT];
__device__ __half g_xh[NROWS * DCAT];
__device__ __half g_wt[(size_t)NPAD * DCAT];   // W transposed, fp16, zero-padded
__device__ int    g_mask_flags;

// ---- mask dtype detection ----
__global__ void reset_flags_kernel() { g_mask_flags = 0; }

__global__ void detect_mask_kernel(const unsigned char* __restrict__ p, int nbytes) {
    int fl = 0;
    for (int i = blockIdx.x * blockDim.x + threadIdx.x; i < nbytes;
         i += gridDim.x * blockDim.x) {
        unsigned char v = p[i];
        if (v > 1) fl |= 2;
        else if (v == 1 && (i & 3)) fl |= 1;
    }
    if (fl) atomicOr(&g_mask_flags, fl);
}

__device__ __forceinline__ int mask_fmt() {
    int f = g_mask_flags;
    return (f & 2) ? 2 : ((f & 1) ? 1 : 0);
}
__device__ __forceinline__ bool mask_at(const void* m, int fmt, long idx) {
    if (fmt == 0) return ((const int*)m)[idx] != 0;
    if (fmt == 1) return ((const unsigned char*)m)[idx] != 0;
    return ((const float*)m)[idx] != 0.0f;
}

// ---- W -> Wt fp16 transpose: Wt[n][k] = (half)W[k][n], n >= VOCAB -> 0 ----
__global__ __launch_bounds__(256) void convert_w_kernel(
    const float* __restrict__ W, __half* __restrict__ Wt)
{
    __shared__ float t[32][33];
    int n0 = blockIdx.x * 32, k0 = blockIdx.y * 32;
    int tx = threadIdx.x & 31, ty = threadIdx.x >> 5;   // 32 x 8
    #pragma unroll
    for (int i = 0; i < 32; i += 8) {
        int k = k0 + ty + i, n = n0 + tx;
        t[ty + i][tx] = (k < DCAT && n < VOCAB) ? W[(size_t)k * VOCAB + n] : 0.0f;
    }
    __syncthreads();
    #pragma unroll
    for (int i = 0; i < 32; i += 8) {
        int n = n0 + ty + i, k = k0 + tx;
        if (k < DCAT)
            Wt[(size_t)n * DCAT + k] = __float2half_rn(t[tx][ty + i]);
    }
}

// ---- x fp32 -> fp16 ----
__global__ __launch_bounds__(256) void convert_x_kernel(
    const float* __restrict__ x, __half* __restrict__ xh)
{
    int i = blockIdx.x * 256 + threadIdx.x;
    if (i < NROWS * DCAT) xh[i] = __float2half_rn(x[i]);
}

// ---- embedding gather + masked node average ----
__global__ __launch_bounds__(256) void embed_kernel(
    const int* __restrict__ code, const int* __restrict__ pos,
    const void* __restrict__ mask, const float* __restrict__ table,
    float* __restrict__ x)
{
    int row = blockIdx.x;
    int b = row >> 9;
    int tid = threadIdx.x;
    long xb = (long)row * DCAT;

    if (pos[row] != 0) {
        long co = (long)code[row] * DEMB;
        #pragma unroll
        for (int l = 0; l < 3; l++) x[xb + tid + l * 256] = table[co + tid + l * 256];
    } else {
        __shared__ int codes[SEQ];
        __shared__ unsigned char flags[SEQ];
        __shared__ int cnt;
        if (tid == 0) cnt = 0;
        __syncthreads();
        int fmt = mask_fmt();
        int local = 0;
        for (int j = tid; j < SEQ; j += 256) {
            bool f = (pos[(b << 9) + j] >= 2) && mask_at(mask, fmt, (long)row * SEQ + j);
            flags[j] = f ? 1 : 0;
            codes[j] = code[(b << 9) + j];
            if (f) local++;
        }
        if (local) atomicAdd(&cnt, local);
        __syncthreads();
        float inv = 1.0f / ((float)cnt + 1e-10f);
        float a0 = 0.f, a1 = 0.f, a2 = 0.f;
        for (int j = 0; j < SEQ; j++) {
            if (flags[j]) {
                const float* er = table + (long)codes[j] * DEMB;
                a0 += er[tid]; a1 += er[tid + 256]; a2 += er[tid + 512];
            }
        }
        x[xb + tid] = a0 * inv; x[xb + tid + 256] = a1 * inv; x[xb + tid + 512] = a2 * inv;
    }
}

// ---- M = D^-1 A ----
__global__ __launch_bounds__(128) void build_m_kernel(
    const void* __restrict__ mask, float* __restrict__ M1)
{
    int row = blockIdx.x;
    int i = row & (SEQ - 1);
    int tid = threadIdx.x;
    int fmt = mask_fmt();
    long base = (long)row * SEQ;
    __shared__ float red[128];

    float s = 0.f;
    for (int j = tid; j < SEQ; j += 128)
        s += (j == i) ? 1.0f : (mask_at(mask, fmt, base + j) ? 1.0f : 0.0f);
    red[tid] = s;
    __syncthreads();
    #pragma unroll
    for (int off = 64; off > 0; off >>= 1) {
        if (tid < off) red[tid] += red[tid + off];
        __syncthreads();
    }
    float inv = 1.0f / red[0];
    for (int j = tid; j < SEQ; j += 128) {
        float a = (j == i) ? 1.0f : (mask_at(mask, fmt, base + j) ? 1.0f : 0.0f);
        M1[base + j] = a * inv;
    }
}

__device__ __forceinline__ uint32_t f2tf32(float f) {
    uint32_t u;
    asm("cvt.rna.tf32.f32 %0, %1;" : "=r"(u) : "f"(f));
    return u;
}

// ---- power GEMM (tf32 128x128, for M^k) ----
__global__ __launch_bounds__(256, 2) void gemm_tf32_kernel(
    const float* __restrict__ A, const float* __restrict__ B,
    float* __restrict__ C, int K, long strideM)
{
    __shared__ float As[2][128][20];
    __shared__ float Bs[2][16][136];

    A += blockIdx.z * strideM;
    B += blockIdx.z * strideM;
    C += blockIdx.z * strideM;

    const int m0 = blockIdx.x * 128;
    const int n0 = blockIdx.y * 128;
    const int tid = threadIdx.x;
    const int lane = tid & 31, warp = tid >> 5;
    const int wm = (warp >> 2) * 64;
    const int wn = (warp & 3) * 32;
    const int g = lane >> 2, t4 = lane & 3;

    float acc[4][4][4];
    #pragma unroll
    for (int a = 0; a < 4; a++)
        #pragma unroll
        for (int bq = 0; bq < 4; bq++)
            #pragma unroll
            for (int c = 0; c < 4; c++) acc[a][bq][c] = 0.f;

    const int KT = K >> 4;
    float4 ra[2];
    float  rb[8];

    auto ldg_tiles = [&](int kt) {
        #pragma unroll
        for (int l = 0; l < 2; l++) {
            int idx = tid + l * 256;
            int ar = idx >> 2, ak = (idx & 3) << 2;
            ra[l] = *reinterpret_cast<const float4*>(
                A + (size_t)(m0 + ar) * SEQ + (kt * 16 + ak));
        }
        #pragma unroll
        for (int l = 0; l < 8; l++) {
            int idx = tid + l * 256;
            rb[l] = B[(size_t)(kt * 16 + (idx >> 7)) * SEQ + n0 + (idx & 127)];
        }
    };
    auto sts_tiles = [&](int buf) {
        #pragma unroll
        for (int l = 0; l < 2; l++) {
            int idx = tid + l * 256;
            int ar = idx >> 2, ak = (idx & 3) << 2;
            As[buf][ar][ak + 0] = __uint_as_float(f2tf32(ra[l].x));
            As[buf][ar][ak + 1] = __uint_as_float(f2tf32(ra[l].y));
            As[buf][ar][ak + 2] = __uint_as_float(f2tf32(ra[l].z));
            As[buf][ar][ak + 3] = __uint_as_float(f2tf32(ra[l].w));
        }
        #pragma unroll
        for (int l = 0; l < 8; l++) {
            int idx = tid + l * 256;
            Bs[buf][idx >> 7][idx & 127] = __uint_as_float(f2tf32(rb[l]));
        }
    };
    auto compute = [&](int buf) {
        #pragma unroll
        for (int ks = 0; ks < 2; ks++) {
            uint32_t af[4][4];
            int k = ks * 8 + t4;
            #pragma unroll
            for (int tm = 0; tm < 4; tm++) {
                int r = wm + tm * 16 + g;
                af[tm][0] = __float_as_uint(As[buf][r][k]);
                af[tm][1] = __float_as_uint(As[buf][r + 8][k]);
                af[tm][2] = __float_as_uint(As[buf][r][k + 4]);
                af[tm][3] = __float_as_uint(As[buf][r + 8][k + 4]);
            }
            uint32_t bf[4][2];
            #pragma unroll
            for (int tn = 0; tn < 4; tn++) {
                int c = wn + tn * 8 + g;
                bf[tn][0] = __float_as_uint(Bs[buf][k][c]);
                bf[tn][1] = __float_as_uint(Bs[buf][k + 4][c]);
            }
            #pragma unroll
            for (int tm = 0; tm < 4; tm++)
                #pragma unroll
                for (int tn = 0; tn < 4; tn++)
                    asm volatile(
                        "mma.sync.aligned.m16n8k8.row.col.f32.tf32.tf32.f32 "
                        "{%0,%1,%2,%3}, {%4,%5,%6,%7}, {%8,%9}, {%0,%1,%2,%3};\n"
                        : "+f"(acc[tm][tn][0]), "+f"(acc[tm][tn][1]),
                          "+f"(acc[tm][tn][2]), "+f"(acc[tm][tn][3])
                        : "r"(af[tm][0]), "r"(af[tm][1]),
                          "r"(af[tm][2]), "r"(af[tm][3]),
                          "r"(bf[tn][0]), "r"(bf[tn][1]));
        }
    };

    ldg_tiles(0);
    sts_tiles(0);
    __syncthreads();
    for (int kt = 0; kt < KT; kt++) {
        if (kt + 1 < KT) ldg_tiles(kt + 1);
        compute(kt & 1);
        if (kt + 1 < KT) sts_tiles((kt + 1) & 1);
        __syncthreads();
    }

    #pragma unroll
    for (int tm = 0; tm < 4; tm++) {
        int r = m0 + wm + tm * 16 + g;
        #pragma unroll
        for (int tn = 0; tn < 4; tn++) {
            int c = n0 + wn + tn * 8 + (t4 << 1);
            C[(size_t)r * SEQ + c]           = acc[tm][tn][0];
            C[(size_t)r * SEQ + c + 1]       = acc[tm][tn][1];
            C[(size_t)(r + 8) * SEQ + c]     = acc[tm][tn][2];
            C[(size_t)(r + 8) * SEQ + c + 1] = acc[tm][tn][3];
        }
    }
}

// ---- final GEMM fp16: 128x256 tile, 5-stage cp.async, m16n8k16 ----
// smem (half units): A stage 128*24, B stage 256*24
#define SA_H (128 * 24)
#define SB_H (256 * 24)
#define NSTG 5

__global__ __launch_bounds__(256, 1) void gemm_final_fp16(
    const __half* __restrict__ A, const __half* __restrict__ B,
    float* __restrict__ C, const float* __restrict__ bias)
{
    extern __shared__ __half sm[];
    __half* sA = sm;
    __half* sB = sm + NSTG * SA_H;

    const int m0 = blockIdx.x * 128;
    const int n0 = blockIdx.y * 256;
    const int tid = threadIdx.x;
    const int lane = tid & 31, warp = tid >> 5;
    const int wm = (warp >> 2) * 64;
    const int wn = (warp & 3) * 64;
    const int g = lane >> 2, t4 = lane & 3;

    uint32_t sA_u = (uint32_t)__cvta_generic_to_shared(sA);
    uint32_t sB_u = (uint32_t)__cvta_generic_to_shared(sB);

    float acc[4][8][4];
    #pragma unroll
    for (int a = 0; a < 4; a++)
        #pragma unroll
        for (int b = 0; b < 8; b++)
            #pragma unroll
            for (int c = 0; c < 4; c++) acc[a][b][c] = 0.f;

    const int KT = DCAT / 16;   // 49

    // A: 128 rows x 16 halves (32B) = 256 x 16B ops -> 1/thread
    // B: 256 rows x 16 halves        = 512 x 16B ops -> 2/thread
    auto load_stage = [&](int stg, int kt) {
        {
            int ar = tid >> 1, ak = (tid & 1) << 3;          // 0 or 8
            const __half* src = A + (size_t)(m0 + ar) * DCAT + kt * 16 + ak;
            uint32_t dst = sA_u + (uint32_t)((stg * SA_H + ar * 24 + ak) * 2);
            asm volatile("cp.async.cg.shared.global [%0], [%1], 16;\n"
                         :: "r"(dst), "l"(src));
        }
        #pragma unroll
        for (int l = 0; l < 2; l++) {
            int idx = tid + l * 256;
            int bn = idx >> 1, bk = (idx & 1) << 3;
            const __half* src = B + (size_t)(n0 + bn) * DCAT + kt * 16 + bk;
            uint32_t dst = sB_u + (uint32_t)((stg * SB_H + bn * 24 + bk) * 2);
            asm volatile("cp.async.cg.shared.global [%0], [%1], 16;\n"
                         :: "r"(dst), "l"(src));
        }
    };

    auto compute = [&](int buf) {
        const uint32_t* a0 = (const uint32_t*)(sA + buf * SA_H);
        const uint32_t* b0 = (const uint32_t*)(sB + buf * SB_H);
        uint32_t af[4][4];
        #pragma unroll
        for (int tm = 0; tm < 4; tm++) {
            int r = wm + tm * 16 + g;
            af[tm][0] = a0[(r * 24 + 2 * t4) >> 1];
            af[tm][1] = a0[((r + 8) * 24 + 2 * t4) >> 1];
            af[tm][2] = a0[(r * 24 + 2 * t4 + 8) >> 1];
            af[tm][3] = a0[((r + 8) * 24 + 2 * t4 + 8) >> 1];
        }
        uint32_t bf[8][2];
        #pragma unroll
        for (int tn = 0; tn < 8; tn++) {
            int c = wn + tn * 8 + g;
            bf[tn][0] = b0[(c * 24 + 2 * t4) >> 1];
            bf[tn][1] = b0[(c * 24 + 2 * t4 + 8) >> 1];
        }
        #pragma unroll
        for (int tm = 0; tm < 4; tm++)
            #pragma unroll
            for (int tn = 0; tn < 8; tn++)
                asm volatile(
                    "mma.sync.aligned.m16n8k16.row.col.f32.f16.f16.f32 "
                    "{%0,%1,%2,%3}, {%4,%5,%6,%7}, {%8,%9}, {%0,%1,%2,%3};\n"
                    : "+f"(acc[tm][tn][0]), "+f"(acc[tm][tn][1]),
                      "+f"(acc[tm][tn][2]), "+f"(acc[tm][tn][3])
                    : "r"(af[tm][0]), "r"(af[tm][1]),
                      "r"(af[tm][2]), "r"(af[tm][3]),
                      "r"(bf[tn][0]), "r"(bf[tn][1]));
    };

    #pragma unroll
    for (int s = 0; s < NSTG - 1; s++) {
        load_stage(s, s);
        asm volatile("cp.async.commit_group;\n" ::: "memory");
    }
    for (int kt = 0; kt < KT; kt++) {
        asm volatile("cp.async.wait_group %0;\n" :: "n"(NSTG - 2) : "memory");
        __syncthreads();
        int nkt = kt + NSTG - 1;
        if (nkt < KT) load_stage(nkt % NSTG, nkt);
        asm volatile("cp.async.commit_group;\n" ::: "memory");
        compute(kt % NSTG);
    }

    #pragma unroll
    for (int tm = 0; tm < 4; tm++) {
        int r = m0 + wm + tm * 16 + g;
        #pragma unroll
        for (int tn = 0; tn < 8; tn++) {
            int c = n0 + wn + tn * 8 + (t4 << 1);
            if (c < VOCAB) {
                float bv = bias[c];
                C[(size_t)r * VOCAB + c]       = acc[tm][tn][0] + bv;
                C[(size_t)(r + 8) * VOCAB + c] = acc[tm][tn][2] + bv;
            }
            if (c + 1 < VOCAB) {
                float bv = bias[c + 1];
                C[(size_t)r * VOCAB + c + 1]       = acc[tm][tn][1] + bv;
                C[(size_t)(r + 8) * VOCAB + c + 1] = acc[tm][tn][3] + bv;
            }
        }
    }
}

// ---- diag(M^k) k=1..16 ----
__global__ __launch_bounds__(128) void diag_pe_kernel(
    const float* __restrict__ M1, const float* __restrict__ M2,
    const float* __restrict__ M3, const float* __restrict__ M4,
    const float* __restrict__ M8, const float* __restrict__ M12,
    float* __restrict__ x)
{
    int row = blockIdx.x;
    int b = row >> 9, i = row & (SEQ - 1);
    int tid = threadIdx.x, lane = tid & 31, warp = tid >> 5;
    long base = (long)row * SEQ;
    long mb   = (long)b * SEQ * SEQ;

    __shared__ float rws[4][SEQ];
    __shared__ float cls[3][SEQ];
    __shared__ float wred[10][4];

    for (int j = tid; j < SEQ; j += 128) {
        rws[0][j] = M1[base + j];
        rws[1][j] = M2[base + j];
        rws[2][j] = M3[base + j];
        rws[3][j] = M4[base + j];
        cls[0][j] = M4 [mb + (long)j * SEQ + i];
        cls[1][j] = M8 [mb + (long)j * SEQ + i];
        cls[2][j] = M12[mb + (long)j * SEQ + i];
    }
    __syncthreads();

    float part[10];
    #pragma unroll
    for (int p = 0; p < 10; p++) part[p] = 0.f;
    for (int j = tid; j < SEQ; j += 128) {
        float a1 = rws[0][j], a2 = rws[1][j], a3 = rws[2][j], a4 = rws[3][j];
        float c4 = cls[0][j], c8 = cls[1][j], c12 = cls[2][j];
        part[0] += a1 * c4;   part[1] += a2 * c4;   part[2] += a3 * c4;
        part[3] += a1 * c8;   part[4] += a2 * c8;   part[5] += a3 * c8;
        part[6] += a1 * c12;  part[7] += a2 * c12;  part[8] += a3 * c12;
        part[9] += a4 * c12;
    }
    #pragma unroll
    for (int p = 0; p < 10; p++) {
        float v = part[p];
        #pragma unroll
        for (int off = 16; off > 0; off >>= 1) v += __shfl_down_sync(0xffffffffu, v, off);
        if (lane == 0) wred[p][warp] = v;
    }
    __syncthreads();

    long xb = (long)row * DCAT + DEMB;
    if (tid < 10) {
        const int slot[10] = {4, 5, 6, 8, 9, 10, 12, 13, 14, 15};
        x[xb + slot[tid]] = wred[tid][0] + wred[tid][1] + wred[tid][2] + wred[tid][3];
    }
    if (tid == 0) {
        x[xb + 0]  = rws[0][i];
        x[xb + 1]  = rws[1][i];
        x[xb + 2]  = rws[2][i];
        x[xb + 3]  = rws[3][i];
        x[xb + 7]  = cls[1][i];
        x[xb + 11] = cls[2][i];
    }
}

extern "C" void kernel_launch(void* const* d_in, const int* in_sizes, int n_in,
                              void* d_out, int out_size)
{
    const int*   code  = (const int*)d_in[0];
    const int*   pos   = (const int*)d_in[1];
    const void*  mask  = d_in[2];
    const float* table = (const float*)d_in[3];
    const float* W     = (const float*)d_in[4];
    const float* bias  = (const float*)d_in[5];
    float* out = (float*)d_out;

    float *pM1, *pM2, *pM3, *pM4, *pM8, *pM12, *px;
    __half *pxh, *pwt;
    cudaGetSymbolAddress((void**)&pM1,  g_M1);
    cudaGetSymbolAddress((void**)&pM2,  g_M2);
    cudaGetSymbolAddress((void**)&pM3,  g_M3);
    cudaGetSymbolAddress((void**)&pM4,  g_M4);
    cudaGetSymbolAddress((void**)&pM8,  g_M8);
    cudaGetSymbolAddress((void**)&pM12, g_M12);
    cudaGetSymbolAddress((void**)&px,   g_x);
    cudaGetSymbolAddress((void**)&pxh,  g_xh);
    cudaGetSymbolAddress((void**)&pwt,  g_wt);

    const long MS = (long)SEQ * SEQ;
    const int  FSMEM = NSTG * (SA_H + SB_H) * 2;   // 92160 B

    cudaFuncSetAttribute(gemm_final_fp16,
                         cudaFuncAttributeMaxDynamicSharedMemorySize, FSMEM);

    reset_flags_kernel<<<1, 1>>>();
    detect_mask_kernel<<<64, 256>>>((const unsigned char*)mask, in_sizes[2]);

    dim3 gW((NPAD + 31) / 32, (DCAT + 31) / 32);   // (1576, 25)
    convert_w_kernel<<<gW, 256>>>(W, pwt);

    embed_kernel<<<NROWS, 256>>>(code, pos, mask, table, px);
    build_m_kernel<<<NROWS, 128>>>(mask, pM1);

    dim3 gP(SEQ / 128, SEQ / 128, BATCH);
    gemm_tf32_kernel<<<gP, 256>>>(pM1, pM1, pM2,  SEQ, MS);
    gemm_tf32_kernel<<<gP, 256>>>(pM2, pM1, pM3,  SEQ, MS);
    gemm_tf32_kernel<<<gP, 256>>>(pM2, pM2, pM4,  SEQ, MS);
    gemm_tf32_kernel<<<gP, 256>>>(pM4, pM4, pM8,  SEQ, MS);
    gemm_tf32_kernel<<<gP, 256>>>(pM8, pM4, pM12, SEQ, MS);

    diag_pe_kernel<<<NROWS, 128>>>(pM1, pM2, pM3, pM4, pM8, pM12, px);

    convert_x_kernel<<<(NROWS * DCAT + 255) / 256, 256>>>(px, pxh);

    dim3 gF(NROWS / 128, NPAD / 256, 1);   // (16, 197)
    gemm_final_fp16<<<gF, 256, FSMEM>>>(pxh, pwt, out, bias);
}

// round 9
// speedup vs baseline: 1.4319x; 1.4319x over previous
#include <cuda_runtime.h>
#include <cuda_fp16.h>
#include <cstdint>

#define SEQ   512
#define BATCH 4
#define NROWS (BATCH * SEQ)
#define DEMB  768
#define DCAT  784
#define KPAD  832             // 13 chunks of 64 halves
#define KCHUNKS 13
#define VOCAB 50265
#define NPAD  50432           // 197 * 256
#define MSZ   (BATCH * SEQ * SEQ)

// chunked layouts (halves): A chunk = 128 rows x 64 halves = 8192; B chunk = 256 x 64 = 16384
#define ACH 8192
#define BCH 16384

__device__ float  g_M1 [MSZ];
__device__ float  g_M2 [MSZ];
__device__ float  g_M3 [MSZ];
__device__ float  g_M4 [MSZ];
__device__ float  g_M8 [MSZ];
__device__ float  g_M12[MSZ];
__device__ float  g_x[NROWS * DCAT];
__device__ __half g_xh[(size_t)(NROWS / 128) * KCHUNKS * ACH];
__device__ __half g_wt[(size_t)(NPAD / 256) * KCHUNKS * BCH];
__device__ int    g_mask_flags;

// ================= helpers =================
__device__ __forceinline__ uint32_t smem_u32(const void* p) {
    uint32_t a;
    asm("{ .reg .u64 t; cvta.to.shared.u64 t, %1; cvt.u32.u64 %0, t; }"
        : "=r"(a) : "l"(p));
    return a;
}
// swizzled half-index within a chunk row layout (row-major, 128B rows,
// 16B blocks XORed with row&7): returns HALF index
__device__ __host__ __forceinline__ uint32_t swz_half(int r, int kh) {
    return (uint32_t)(r * 64 + ((((kh >> 3) ^ r) & 7) << 3) + (kh & 7));
}
__device__ __forceinline__ void mbar_init(uint32_t a, uint32_t cnt) {
    asm volatile("mbarrier.init.shared.b64 [%0], %1;" :: "r"(a), "r"(cnt) : "memory");
}
__device__ __forceinline__ void mbar_expect_tx(uint32_t a, uint32_t bytes) {
    asm volatile("mbarrier.arrive.expect_tx.shared.b64 _, [%0], %1;"
                 :: "r"(a), "r"(bytes) : "memory");
}
__device__ __forceinline__ void bulk_g2s(uint32_t dst, const void* src,
                                         uint32_t bytes, uint32_t mbar) {
    asm volatile(
        "cp.async.bulk.shared::cluster.global.mbarrier::complete_tx::bytes "
        "[%0], [%1], %2, [%3];"
        :: "r"(dst), "l"(src), "r"(bytes), "r"(mbar) : "memory");
}
__device__ __forceinline__ void mbar_wait(uint32_t a, uint32_t ph) {
    uint32_t done;
    asm volatile(
        "{\n\t.reg .pred p;\n\t"
        "mbarrier.try_wait.parity.acquire.cta.shared::cta.b64 p, [%1], %2;\n\t"
        "selp.b32 %0, 1, 0, p;\n\t}"
        : "=r"(done) : "r"(a), "r"(ph) : "memory");
    if (!done) {
        asm volatile(
            "{\n\t.reg .pred P1;\n\t"
            "WL_%=:\n\t"
            "mbarrier.try_wait.parity.acquire.cta.shared::cta.b64 P1, [%0], %1, 0x989680;\n\t"
            "@P1 bra.uni WD_%=;\n\t"
            "bra.uni WL_%=;\n\t"
            "WD_%=:\n\t}"
            :: "r"(a), "r"(ph) : "memory");
    }
}

// ================= mask dtype detection =================
__global__ void reset_flags_kernel() { g_mask_flags = 0; }

__global__ __launch_bounds__(256) void detect_mask_kernel(
    const uint4* __restrict__ p, int nvec)
{
    int fl = 0;
    for (int i = blockIdx.x * blockDim.x + threadIdx.x; i < nvec;
         i += gridDim.x * blockDim.x) {
        uint4 v = p[i];
        uint32_t any = v.x | v.y | v.z | v.w;
        if (any & 0xFEFEFEFEu) fl |= 2;            // byte > 1 -> float32
        else if (any & 0x01010100u) fl |= 1;       // 1 at unaligned byte -> int8
    }
    if (fl) atomicOr(&g_mask_flags, fl);
}

__device__ __forceinline__ int mask_fmt() {
    int f = g_mask_flags;
    return (f & 2) ? 2 : ((f & 1) ? 1 : 0);
}
__device__ __forceinline__ bool mask_at(const void* m, int fmt, long idx) {
    if (fmt == 0) return ((const int*)m)[idx] != 0;
    if (fmt == 1) return ((const unsigned char*)m)[idx] != 0;
    return ((const float*)m)[idx] != 0.0f;
}

// ================= W -> chunked swizzled fp16 =================
__global__ __launch_bounds__(256) void convert_w_kernel(
    const float* __restrict__ W, __half* __restrict__ Wt)
{
    __shared__ float t[32][33];
    int n0 = blockIdx.x * 32, k0 = blockIdx.y * 32;
    int tx = threadIdx.x & 31, ty = threadIdx.x >> 5;
    #pragma unroll
    for (int i = 0; i < 32; i += 8) {
        int k = k0 + ty + i, n = n0 + tx;
        t[ty + i][tx] = (k < DCAT && n < VOCAB) ? W[(size_t)k * VOCAB + n] : 0.0f;
    }
    __syncthreads();
    #pragma unroll
    for (int i = 0; i < 32; i += 8) {
        int n = n0 + ty + i, k = k0 + tx;
        int ntile = n >> 8, rr = n & 255;
        int kc = k >> 6, kh = k & 63;
        size_t base = ((size_t)ntile * KCHUNKS + kc) * BCH;
        Wt[base + swz_half(rr, kh)] = __float2half_rn(t[tx][ty + i]);
    }
}

// ================= x -> chunked swizzled fp16 =================
__global__ __launch_bounds__(256) void convert_x_kernel(
    const float* __restrict__ x, __half* __restrict__ xh)
{
    int i = blockIdx.x * 256 + threadIdx.x;
    if (i < NROWS * KPAD) {
        int row = i / KPAD, khg = i - row * KPAD;
        int mtile = row >> 7, r = row & 127;
        int kc = khg >> 6, kh = khg & 63;
        size_t base = ((size_t)mtile * KCHUNKS + kc) * ACH;
        float v = (khg < DCAT) ? x[(size_t)row * DCAT + khg] : 0.0f;
        xh[base + swz_half(r, kh)] = __float2half_rn(v);
    }
}

// ================= embedding gather + masked node average =================
__global__ __launch_bounds__(256) void embed_kernel(
    const int* __restrict__ code, const int* __restrict__ pos,
    const void* __restrict__ mask, const float* __restrict__ table,
    float* __restrict__ x)
{
    int row = blockIdx.x;
    int b = row >> 9;
    int tid = threadIdx.x;
    long xb = (long)row * DCAT;

    if (pos[row] != 0) {
        long co = (long)code[row] * DEMB;
        #pragma unroll
        for (int l = 0; l < 3; l++) x[xb + tid + l * 256] = table[co + tid + l * 256];
    } else {
        __shared__ int list[SEQ];
        __shared__ int cnt;
        if (tid == 0) cnt = 0;
        __syncthreads();
        int fmt = mask_fmt();
        for (int j = tid; j < SEQ; j += 256) {
            bool f = (pos[(b << 9) + j] >= 2) && mask_at(mask, fmt, (long)row * SEQ + j);
            if (f) { int k = atomicAdd(&cnt, 1); list[k] = code[(b << 9) + j]; }
        }
        __syncthreads();
        int n = cnt;
        float inv = 1.0f / ((float)n + 1e-10f);
        float a0 = 0.f, a1 = 0.f, a2 = 0.f;
        int jj = 0;
        for (; jj + 4 <= n; jj += 4) {
            const float* e0 = table + (long)list[jj] * DEMB;
            const float* e1 = table + (long)list[jj + 1] * DEMB;
            const float* e2 = table + (long)list[jj + 2] * DEMB;
            const float* e3 = table + (long)list[jj + 3] * DEMB;
            a0 += e0[tid] + e1[tid] + e2[tid] + e3[tid];
            a1 += e0[tid + 256] + e1[tid + 256] + e2[tid + 256] + e3[tid + 256];
            a2 += e0[tid + 512] + e1[tid + 512] + e2[tid + 512] + e3[tid + 512];
        }
        for (; jj < n; jj++) {
            const float* e0 = table + (long)list[jj] * DEMB;
            a0 += e0[tid]; a1 += e0[tid + 256]; a2 += e0[tid + 512];
        }
        x[xb + tid] = a0 * inv; x[xb + tid + 256] = a1 * inv; x[xb + tid + 512] = a2 * inv;
    }
}

// ================= M = D^-1 A =================
__global__ __launch_bounds__(128) void build_m_kernel(
    const void* __restrict__ mask, float* __restrict__ M1)
{
    int row = blockIdx.x;
    int i = row & (SEQ - 1);
    int tid = threadIdx.x;
    int fmt = mask_fmt();
    long base = (long)row * SEQ;
    __shared__ float red[128];

    float s = 0.f;
    for (int j = tid; j < SEQ; j += 128)
        s += (j == i) ? 1.0f : (mask_at(mask, fmt, base + j) ? 1.0f : 0.0f);
    red[tid] = s;
    __syncthreads();
    #pragma unroll
    for (int off = 64; off > 0; off >>= 1) {
        if (tid < off) red[tid] += red[tid + off];
        __syncthreads();
    }
    float inv = 1.0f / red[0];
    for (int j = tid; j < SEQ; j += 128) {
        float a = (j == i) ? 1.0f : (mask_at(mask, fmt, base + j) ? 1.0f : 0.0f);
        M1[base + j] = a * inv;
    }
}

__device__ __forceinline__ uint32_t f2tf32(float f) {
    uint32_t u;
    asm("cvt.rna.tf32.f32 %0, %1;" : "=r"(u) : "f"(f));
    return u;
}

// ================= power GEMM (tf32 legacy 128x128) =================
__global__ __launch_bounds__(256, 2) void gemm_tf32_kernel(
    const float* __restrict__ A, const float* __restrict__ B,
    float* __restrict__ C, int K, long strideM)
{
    __shared__ float As[2][128][20];
    __shared__ float Bs[2][16][136];

    A += blockIdx.z * strideM;
    B += blockIdx.z * strideM;
    C += blockIdx.z * strideM;

    const int m0 = blockIdx.x * 128;
    const int n0 = blockIdx.y * 128;
    const int tid = threadIdx.x;
    const int lane = tid & 31, warp = tid >> 5;
    const int wm = (warp >> 2) * 64;
    const int wn = (warp & 3) * 32;
    const int g = lane >> 2, t4 = lane & 3;

    float acc[4][4][4];
    #pragma unroll
    for (int a = 0; a < 4; a++)
        #pragma unroll
        for (int bq = 0; bq < 4; bq++)
            #pragma unroll
            for (int c = 0; c < 4; c++) acc[a][bq][c] = 0.f;

    const int KT = K >> 4;
    float4 ra[2];
    float  rb[8];

    auto ldg_tiles = [&](int kt) {
        #pragma unroll
        for (int l = 0; l < 2; l++) {
            int idx = tid + l * 256;
            int ar = idx >> 2, ak = (idx & 3) << 2;
            ra[l] = *reinterpret_cast<const float4*>(
                A + (size_t)(m0 + ar) * SEQ + (kt * 16 + ak));
        }
        #pragma unroll
        for (int l = 0; l < 8; l++) {
            int idx = tid + l * 256;
            rb[l] = B[(size_t)(kt * 16 + (idx >> 7)) * SEQ + n0 + (idx & 127)];
        }
    };
    auto sts_tiles = [&](int buf) {
        #pragma unroll
        for (int l = 0; l < 2; l++) {
            int idx = tid + l * 256;
            int ar = idx >> 2, ak = (idx & 3) << 2;
            As[buf][ar][ak + 0] = __uint_as_float(f2tf32(ra[l].x));
            As[buf][ar][ak + 1] = __uint_as_float(f2tf32(ra[l].y));
            As[buf][ar][ak + 2] = __uint_as_float(f2tf32(ra[l].z));
            As[buf][ar][ak + 3] = __uint_as_float(f2tf32(ra[l].w));
        }
        #pragma unroll
        for (int l = 0; l < 8; l++) {
            int idx = tid + l * 256;
            Bs[buf][idx >> 7][idx & 127] = __uint_as_float(f2tf32(rb[l]));
        }
    };
    auto compute = [&](int buf) {
        #pragma unroll
        for (int ks = 0; ks < 2; ks++) {
            uint32_t af[4][4];
            int k = ks * 8 + t4;
            #pragma unroll
            for (int tm = 0; tm < 4; tm++) {
                int r = wm + tm * 16 + g;
                af[tm][0] = __float_as_uint(As[buf][r][k]);
                af[tm][1] = __float_as_uint(As[buf][r + 8][k]);
                af[tm][2] = __float_as_uint(As[buf][r][k + 4]);
                af[tm][3] = __float_as_uint(As[buf][r + 8][k + 4]);
            }
            uint32_t bf[4][2];
            #pragma unroll
            for (int tn = 0; tn < 4; tn++) {
                int c = wn + tn * 8 + g;
                bf[tn][0] = __float_as_uint(Bs[buf][k][c]);
                bf[tn][1] = __float_as_uint(Bs[buf][k + 4][c]);
            }
            #pragma unroll
            for (int tm = 0; tm < 4; tm++)
                #pragma unroll
                for (int tn = 0; tn < 4; tn++)
                    asm volatile(
                        "mma.sync.aligned.m16n8k8.row.col.f32.tf32.tf32.f32 "
                        "{%0,%1,%2,%3}, {%4,%5,%6,%7}, {%8,%9}, {%0,%1,%2,%3};\n"
                        : "+f"(acc[tm][tn][0]), "+f"(acc[tm][tn][1]),
                          "+f"(acc[tm][tn][2]), "+f"(acc[tm][tn][3])
                        : "r"(af[tm][0]), "r"(af[tm][1]),
                          "r"(af[tm][2]), "r"(af[tm][3]),
                          "r"(bf[tn][0]), "r"(bf[tn][1]));
        }
    };

    ldg_tiles(0);
    sts_tiles(0);
    __syncthreads();
    for (int kt = 0; kt < KT; kt++) {
        if (kt + 1 < KT) ldg_tiles(kt + 1);
        compute(kt & 1);
        if (kt + 1 < KT) sts_tiles((kt + 1) & 1);
        __syncthreads();
    }

    #pragma unroll
    for (int tm = 0; tm < 4; tm++) {
        int r = m0 + wm + tm * 16 + g;
        #pragma unroll
        for (int tn = 0; tn < 4; tn++) {
            int c = n0 + wn + tn * 8 + (t4 << 1);
            C[(size_t)r * SEQ + c]           = acc[tm][tn][0];
            C[(size_t)r * SEQ + c + 1]       = acc[tm][tn][1];
            C[(size_t)(r + 8) * SEQ + c]     = acc[tm][tn][2];
            C[(size_t)(r + 8) * SEQ + c + 1] = acc[tm][tn][3];
        }
    }
}

// ================= final GEMM: fp16 mma + cp.async.bulk stages =================
#define STG_BYTES (ACH * 2 + BCH * 2)   // 49152
#define NSTAGE 3
#define FSMEM (NSTAGE * STG_BYTES + 1024)

__global__ __launch_bounds__(256, 1) void gemm_final_fp16(
    const __half* __restrict__ A, const __half* __restrict__ B,
    float* __restrict__ C, const float* __restrict__ bias)
{
    extern __shared__ char dynsm[];
    __shared__ __align__(8) uint64_t s_mbar[NSTAGE];

    const int mt = blockIdx.x;
    const int nt = blockIdx.y;
    const int m0 = mt * 128;
    const int n0 = nt * 256;
    const int tid = threadIdx.x;
    const int lane = tid & 31, warp = tid >> 5;
    const int wm = (warp >> 2) * 64;     // 2 warps in M
    const int wn = (warp & 3) * 64;      // 4 warps in N
    const int g = lane >> 2, t4 = lane & 3;

    uint32_t raw_u = smem_u32(dynsm);
    uint32_t base_u = (raw_u + 1023u) & ~1023u;
    char* base_g = dynsm + (base_u - raw_u);

    const __half* Ach = A + (size_t)mt * KCHUNKS * ACH;
    const __half* Bch = B + (size_t)nt * KCHUNKS * BCH;

    uint32_t mb[NSTAGE];
    #pragma unroll
    for (int s = 0; s < NSTAGE; s++) mb[s] = smem_u32(&s_mbar[s]);

    if (tid == 0) {
        #pragma unroll
        for (int s = 0; s < NSTAGE; s++) mbar_init(mb[s], 1);
    }
    __syncthreads();

    if (tid == 0) {
        #pragma unroll
        for (int s = 0; s < NSTAGE; s++) {
            mbar_expect_tx(mb[s], STG_BYTES);
            bulk_g2s(base_u + s * STG_BYTES,            Ach + (size_t)s * ACH, ACH * 2, mb[s]);
            bulk_g2s(base_u + s * STG_BYTES + ACH * 2,  Bch + (size_t)s * BCH, BCH * 2, mb[s]);
        }
    }

    float acc[4][8][4];
    #pragma unroll
    for (int a = 0; a < 4; a++)
        #pragma unroll
        for (int b = 0; b < 8; b++)
            #pragma unroll
            for (int c = 0; c < 4; c++) acc[a][b][c] = 0.f;

    int ph[NSTAGE] = {0, 0, 0};

    for (int kc = 0; kc < KCHUNKS; kc++) {
        int s = kc % NSTAGE;
        mbar_wait(mb[s], ph[s]);
        ph[s] ^= 1;

        const char* a0 = base_g + s * STG_BYTES;
        const char* b0 = a0 + ACH * 2;

        #pragma unroll
        for (int kk = 0; kk < 4; kk++) {
            int kh = kk * 16 + 2 * t4;
            uint32_t af[4][4];
            #pragma unroll
            for (int tm = 0; tm < 4; tm++) {
                int r = wm + tm * 16 + g;
                af[tm][0] = *(const uint32_t*)(a0 + swz_half(r,     kh)     * 2);
                af[tm][1] = *(const uint32_t*)(a0 + swz_half(r + 8, kh)     * 2);
                af[tm][2] = *(const uint32_t*)(a0 + swz_half(r,     kh + 8) * 2);
                af[tm][3] = *(const uint32_t*)(a0 + swz_half(r + 8, kh + 8) * 2);
            }
            uint32_t bf[8][2];
            #pragma unroll
            for (int tn = 0; tn < 8; tn++) {
                int c = wn + tn * 8 + g;
                bf[tn][0] = *(const uint32_t*)(b0 + swz_half(c, kh)     * 2);
                bf[tn][1] = *(const uint32_t*)(b0 + swz_half(c, kh + 8) * 2);
            }
            #pragma unroll
            for (int tm = 0; tm < 4; tm++)
                #pragma unroll
                for (int tn = 0; tn < 8; tn++)
                    asm volatile(
                        "mma.sync.aligned.m16n8k16.row.col.f32.f16.f16.f32 "
                        "{%0,%1,%2,%3}, {%4,%5,%6,%7}, {%8,%9}, {%0,%1,%2,%3};\n"
                        : "+f"(acc[tm][tn][0]), "+f"(acc[tm][tn][1]),
                          "+f"(acc[tm][tn][2]), "+f"(acc[tm][tn][3])
                        : "r"(af[tm][0]), "r"(af[tm][1]),
                          "r"(af[tm][2]), "r"(af[tm][3]),
                          "r"(bf[tn][0]), "r"(bf[tn][1]));
        }

        __syncthreads();   // all warps done reading stage s
        int nkc = kc + NSTAGE;
        if (nkc < KCHUNKS && tid == 0) {
            mbar_expect_tx(mb[s], STG_BYTES);
            bulk_g2s(base_u + s * STG_BYTES,           Ach + (size_t)nkc * ACH, ACH * 2, mb[s]);
            bulk_g2s(base_u + s * STG_BYTES + ACH * 2, Bch + (size_t)nkc * BCH, BCH * 2, mb[s]);
        }
    }

    #pragma unroll
    for (int tm = 0; tm < 4; tm++) {
        int r = m0 + wm + tm * 16 + g;
        #pragma unroll
        for (int tn = 0; tn < 8; tn++) {
            int c = n0 + wn + tn * 8 + (t4 << 1);
            if (c < VOCAB) {
                float bv = bias[c];
                C[(size_t)r * VOCAB + c]       = acc[tm][tn][0] + bv;
                C[(size_t)(r + 8) * VOCAB + c] = acc[tm][tn][2] + bv;
            }
            if (c + 1 < VOCAB) {
                float bv = bias[c + 1];
                C[(size_t)r * VOCAB + c + 1]       = acc[tm][tn][1] + bv;
                C[(size_t)(r + 8) * VOCAB + c + 1] = acc[tm][tn][3] + bv;
            }
        }
    }
}

// ================= diag(M^k) k=1..16 =================
__global__ __launch_bounds__(128) void diag_pe_kernel(
    const float* __restrict__ M1, const float* __restrict__ M2,
    const float* __restrict__ M3, const float* __restrict__ M4,
    const float* __restrict__ M8, const float* __restrict__ M12,
    float* __restrict__ x)
{
    int row = blockIdx.x;
    int b = row >> 9, i = row & (SEQ - 1);
    int tid = threadIdx.x, lane = tid & 31, warp = tid >> 5;
    long base = (long)row * SEQ;
    long mbq  = (long)b * SEQ * SEQ;

    __shared__ float rws[4][SEQ];
    __shared__ float cls[3][SEQ];
    __shared__ float wred[10][4];

    for (int j = tid; j < SEQ; j += 128) {
        rws[0][j] = M1[base + j];
        rws[1][j] = M2[base + j];
        rws[2][j] = M3[base + j];
        rws[3][j] = M4[base + j];
        cls[0][j] = M4 [mbq + (long)j * SEQ + i];
        cls[1][j] = M8 [mbq + (long)j * SEQ + i];
        cls[2][j] = M12[mbq + (long)j * SEQ + i];
    }
    __syncthreads();

    float part[10];
    #pragma unroll
    for (int p = 0; p < 10; p++) part[p] = 0.f;
    for (int j = tid; j < SEQ; j += 128) {
        float a1 = rws[0][j], a2 = rws[1][j], a3 = rws[2][j], a4 = rws[3][j];
        float c4 = cls[0][j], c8 = cls[1][j], c12 = cls[2][j];
        part[0] += a1 * c4;   part[1] += a2 * c4;   part[2] += a3 * c4;
        part[3] += a1 * c8;   part[4] += a2 * c8;   part[5] += a3 * c8;
        part[6] += a1 * c12;  part[7] += a2 * c12;  part[8] += a3 * c12;
        part[9] += a4 * c12;
    }
    #pragma unroll
    for (int p = 0; p < 10; p++) {
        float v = part[p];
        #pragma unroll
        for (int off = 16; off > 0; off >>= 1) v += __shfl_down_sync(0xffffffffu, v, off);
        if (lane == 0) wred[p][warp] = v;
    }
    __syncthreads();

    long xb = (long)row * DCAT + DEMB;
    if (tid < 10) {
        const int slot[10] = {4, 5, 6, 8, 9, 10, 12, 13, 14, 15};
        x[xb + slot[tid]] = wred[tid][0] + wred[tid][1] + wred[tid][2] + wred[tid][3];
    }
    if (tid == 0) {
        x[xb + 0]  = rws[0][i];
        x[xb + 1]  = rws[1][i];
        x[xb + 2]  = rws[2][i];
        x[xb + 3]  = rws[3][i];
        x[xb + 7]  = cls[1][i];
        x[xb + 11] = cls[2][i];
    }
}

extern "C" void kernel_launch(void* const* d_in, const int* in_sizes, int n_in,
                              void* d_out, int out_size)
{
    const int*   code  = (const int*)d_in[0];
    const int*   pos   = (const int*)d_in[1];
    const void*  mask  = d_in[2];
    const float* table = (const float*)d_in[3];
    const float* W     = (const float*)d_in[4];
    const float* bias  = (const float*)d_in[5];
    float* out = (float*)d_out;

    float *pM1, *pM2, *pM3, *pM4, *pM8, *pM12, *px;
    __half *pxh, *pwt;
    cudaGetSymbolAddress((void**)&pM1,  g_M1);
    cudaGetSymbolAddress((void**)&pM2,  g_M2);
    cudaGetSymbolAddress((void**)&pM3,  g_M3);
    cudaGetSymbolAddress((void**)&pM4,  g_M4);
    cudaGetSymbolAddress((void**)&pM8,  g_M8);
    cudaGetSymbolAddress((void**)&pM12, g_M12);
    cudaGetSymbolAddress((void**)&px,   g_x);
    cudaGetSymbolAddress((void**)&pxh,  g_xh);
    cudaGetSymbolAddress((void**)&pwt,  g_wt);

    const long MS = (long)SEQ * SEQ;

    cudaFuncSetAttribute(gemm_final_fp16,
                         cudaFuncAttributeMaxDynamicSharedMemorySize, FSMEM);

    reset_flags_kernel<<<1, 1>>>();
    detect_mask_kernel<<<64, 256>>>((const uint4*)mask, in_sizes[2] / 16);

    dim3 gW(NPAD / 32, (KPAD + 31) / 32);   // (1576, 26)
    convert_w_kernel<<<gW, 256>>>(W, pwt);

    embed_kernel<<<NROWS, 256>>>(code, pos, mask, table, px);
    build_m_kernel<<<NROWS, 128>>>(mask, pM1);

    dim3 gP(SEQ / 128, SEQ / 128, BATCH);
    gemm_tf32_kernel<<<gP, 256>>>(pM1, pM1, pM2,  SEQ, MS);
    gemm_tf32_kernel<<<gP, 256>>>(pM2, pM1, pM3,  SEQ, MS);
    gemm_tf32_kernel<<<gP, 256>>>(pM2, pM2, pM4,  SEQ, MS);
    gemm_tf32_kernel<<<gP, 256>>>(pM4, pM4, pM8,  SEQ, MS);
    gemm_tf32_kernel<<<gP, 256>>>(pM8, pM4, pM12, SEQ, MS);

    diag_pe_kernel<<<NROWS, 128>>>(pM1, pM2, pM3, pM4, pM8, pM12, px);

    convert_x_kernel<<<(NROWS * KPAD + 255) / 256, 256>>>(px, pxh);

    dim3 gF(NROWS / 128, NPAD / 256, 1);   // (16, 197)
    gemm_final_fp16<<<gF, 256, FSMEM>>>(pxh, pwt, out, bias);
}

// round 10
// speedup vs baseline: 1.5609x; 1.0901x over previous
#include <cuda_runtime.h>
#include <cuda_fp16.h>
#include <cstdint>

#define SEQ   512
#define BATCH 4
#define NROWS (BATCH * SEQ)
#define DEMB  768
#define DCAT  784
#define KPAD  832             // 13 chunks of 64 halves
#define KCHUNKS 13
#define VOCAB 50265
#define NPAD  50432           // 197 * 256
#define MSZ   (BATCH * SEQ * SEQ)

// chunked layouts (halves): A chunk = 128 rows x 64; B chunk = 256 x 64
#define ACH 8192
#define BCH 16384

__device__ float  g_M1 [MSZ];
__device__ float  g_M2 [MSZ];
__device__ float  g_M3 [MSZ];
__device__ float  g_M4 [MSZ];
__device__ float  g_M8 [MSZ];
__device__ float  g_M12[MSZ];
__device__ float  g_x[NROWS * DCAT];
__device__ __half g_xh[(size_t)(NROWS / 128) * KCHUNKS * ACH];
__device__ __half g_wt[(size_t)(NPAD / 256) * KCHUNKS * BCH];
__device__ int    g_mask_flags;

// ================= helpers =================
__device__ __forceinline__ uint32_t smem_u32(const void* p) {
    uint32_t a;
    asm("{ .reg .u64 t; cvta.to.shared.u64 t, %1; cvt.u32.u64 %0, t; }"
        : "=r"(a) : "l"(p));
    return a;
}
__device__ __host__ __forceinline__ uint32_t swz_half(int r, int kh) {
    return (uint32_t)(r * 64 + ((((kh >> 3) ^ r) & 7) << 3) + (kh & 7));
}
__device__ __forceinline__ void mbar_init(uint32_t a, uint32_t cnt) {
    asm volatile("mbarrier.init.shared.b64 [%0], %1;" :: "r"(a), "r"(cnt) : "memory");
}
__device__ __forceinline__ void mbar_expect_tx(uint32_t a, uint32_t bytes) {
    asm volatile("mbarrier.arrive.expect_tx.shared.b64 _, [%0], %1;"
                 :: "r"(a), "r"(bytes) : "memory");
}
__device__ __forceinline__ void mbar_arrive(uint32_t a) {
    asm volatile("mbarrier.arrive.shared.b64 _, [%0];" :: "r"(a) : "memory");
}
__device__ __forceinline__ void bulk_g2s(uint32_t dst, const void* src,
                                         uint32_t bytes, uint32_t mbar) {
    asm volatile(
        "cp.async.bulk.shared::cluster.global.mbarrier::complete_tx::bytes "
        "[%0], [%1], %2, [%3];"
        :: "r"(dst), "l"(src), "r"(bytes), "r"(mbar) : "memory");
}
__device__ __forceinline__ void mbar_wait(uint32_t a, uint32_t ph) {
    uint32_t done;
    asm volatile(
        "{\n\t.reg .pred p;\n\t"
        "mbarrier.try_wait.parity.acquire.cta.shared::cta.b64 p, [%1], %2;\n\t"
        "selp.b32 %0, 1, 0, p;\n\t}"
        : "=r"(done) : "r"(a), "r"(ph) : "memory");
    if (!done) {
        asm volatile(
            "{\n\t.reg .pred P1;\n\t"
            "WL_%=:\n\t"
            "mbarrier.try_wait.parity.acquire.cta.shared::cta.b64 P1, [%0], %1, 0x989680;\n\t"
            "@P1 bra.uni WD_%=;\n\t"
            "bra.uni WL_%=;\n\t"
            "WD_%=:\n\t}"
            :: "r"(a), "r"(ph) : "memory");
    }
}

// ================= mask dtype detection =================
__global__ void reset_flags_kernel() { g_mask_flags = 0; }

__global__ __launch_bounds__(256) void detect_mask_kernel(
    const uint4* __restrict__ p, int nvec)
{
    int fl = 0;
    for (int i = blockIdx.x * blockDim.x + threadIdx.x; i < nvec;
         i += gridDim.x * blockDim.x) {
        uint4 v = p[i];
        uint32_t any = v.x | v.y | v.z | v.w;
        if (any & 0xFEFEFEFEu) fl |= 2;
        else if (any & 0x01010100u) fl |= 1;
    }
    if (fl) atomicOr(&g_mask_flags, fl);
}

__device__ __forceinline__ int mask_fmt() {
    int f = g_mask_flags;
    return (f & 2) ? 2 : ((f & 1) ? 1 : 0);
}
__device__ __forceinline__ bool mask_at(const void* m, int fmt, long idx) {
    if (fmt == 0) return ((const int*)m)[idx] != 0;
    if (fmt == 1) return ((const unsigned char*)m)[idx] != 0;
    return ((const float*)m)[idx] != 0.0f;
}

// ================= W -> chunked swizzled fp16 =================
__global__ __launch_bounds__(256) void convert_w_kernel(
    const float* __restrict__ W, __half* __restrict__ Wt)
{
    __shared__ float t[32][33];
    int n0 = blockIdx.x * 32, k0 = blockIdx.y * 32;
    int tx = threadIdx.x & 31, ty = threadIdx.x >> 5;
    #pragma unroll
    for (int i = 0; i < 32; i += 8) {
        int k = k0 + ty + i, n = n0 + tx;
        t[ty + i][tx] = (k < DCAT && n < VOCAB) ? W[(size_t)k * VOCAB + n] : 0.0f;
    }
    __syncthreads();
    #pragma unroll
    for (int i = 0; i < 32; i += 8) {
        int n = n0 + ty + i, k = k0 + tx;
        int ntile = n >> 8, rr = n & 255;
        int kc = k >> 6, kh = k & 63;
        size_t base = ((size_t)ntile * KCHUNKS + kc) * BCH;
        Wt[base + swz_half(rr, kh)] = __float2half_rn(t[tx][ty + i]);
    }
}

// ================= x -> chunked swizzled fp16 =================
__global__ __launch_bounds__(256) void convert_x_kernel(
    const float* __restrict__ x, __half* __restrict__ xh)
{
    int i = blockIdx.x * 256 + threadIdx.x;
    if (i < NROWS * KPAD) {
        int row = i / KPAD, khg = i - row * KPAD;
        int mtile = row >> 7, r = row & 127;
        int kc = khg >> 6, kh = khg & 63;
        size_t base = ((size_t)mtile * KCHUNKS + kc) * ACH;
        float v = (khg < DCAT) ? x[(size_t)row * DCAT + khg] : 0.0f;
        xh[base + swz_half(r, kh)] = __float2half_rn(v);
    }
}

// ================= embedding gather + masked node average =================
__global__ __launch_bounds__(256) void embed_kernel(
    const int* __restrict__ code, const int* __restrict__ pos,
    const void* __restrict__ mask, const float* __restrict__ table,
    float* __restrict__ x)
{
    int row = blockIdx.x;
    int b = row >> 9;
    int tid = threadIdx.x;
    long xb = (long)row * DCAT;

    if (pos[row] != 0) {
        long co = (long)code[row] * DEMB;
        #pragma unroll
        for (int l = 0; l < 3; l++) x[xb + tid + l * 256] = table[co + tid + l * 256];
    } else {
        __shared__ int list[SEQ];
        __shared__ int cnt;
        if (tid == 0) cnt = 0;
        __syncthreads();
        int fmt = mask_fmt();
        for (int j = tid; j < SEQ; j += 256) {
            bool f = (pos[(b << 9) + j] >= 2) && mask_at(mask, fmt, (long)row * SEQ + j);
            if (f) { int k = atomicAdd(&cnt, 1); list[k] = code[(b << 9) + j]; }
        }
        __syncthreads();
        int n = cnt;
        float inv = 1.0f / ((float)n + 1e-10f);
        float a0 = 0.f, a1 = 0.f, a2 = 0.f;
        int jj = 0;
        for (; jj + 4 <= n; jj += 4) {
            const float* e0 = table + (long)list[jj] * DEMB;
            const float* e1 = table + (long)list[jj + 1] * DEMB;
            const float* e2 = table + (long)list[jj + 2] * DEMB;
            const float* e3 = table + (long)list[jj + 3] * DEMB;
            a0 += e0[tid] + e1[tid] + e2[tid] + e3[tid];
            a1 += e0[tid + 256] + e1[tid + 256] + e2[tid + 256] + e3[tid + 256];
            a2 += e0[tid + 512] + e1[tid + 512] + e2[tid + 512] + e3[tid + 512];
        }
        for (; jj < n; jj++) {
            const float* e0 = table + (long)list[jj] * DEMB;
            a0 += e0[tid]; a1 += e0[tid + 256]; a2 += e0[tid + 512];
        }
        x[xb + tid] = a0 * inv; x[xb + tid + 256] = a1 * inv; x[xb + tid + 512] = a2 * inv;
    }
}

// ================= M = D^-1 A =================
__global__ __launch_bounds__(128) void build_m_kernel(
    const void* __restrict__ mask, float* __restrict__ M1)
{
    int row = blockIdx.x;
    int i = row & (SEQ - 1);
    int tid = threadIdx.x;
    int fmt = mask_fmt();
    long base = (long)row * SEQ;
    __shared__ float red[128];

    float s = 0.f;
    for (int j = tid; j < SEQ; j += 128)
        s += (j == i) ? 1.0f : (mask_at(mask, fmt, base + j) ? 1.0f : 0.0f);
    red[tid] = s;
    __syncthreads();
    #pragma unroll
    for (int off = 64; off > 0; off >>= 1) {
        if (tid < off) red[tid] += red[tid + off];
        __syncthreads();
    }
    float inv = 1.0f / red[0];
    for (int j = tid; j < SEQ; j += 128) {
        float a = (j == i) ? 1.0f : (mask_at(mask, fmt, base + j) ? 1.0f : 0.0f);
        M1[base + j] = a * inv;
    }
}

__device__ __forceinline__ uint32_t f2tf32(float f) {
    uint32_t u;
    asm("cvt.rna.tf32.f32 %0, %1;" : "=r"(u) : "f"(f));
    return u;
}

// ================= power GEMM body (tf32 128x128) =================
__device__ __forceinline__ void gemm_tf32_body(
    const float* __restrict__ A, const float* __restrict__ B,
    float* __restrict__ C, int m0, int n0, int K)
{
    __shared__ float As[2][128][20];
    __shared__ float Bs[2][16][136];

    const int tid = threadIdx.x;
    const int lane = tid & 31, warp = tid >> 5;
    const int wm = (warp >> 2) * 64;
    const int wn = (warp & 3) * 32;
    const int g = lane >> 2, t4 = lane & 3;

    float acc[4][4][4];
    #pragma unroll
    for (int a = 0; a < 4; a++)
        #pragma unroll
        for (int bq = 0; bq < 4; bq++)
            #pragma unroll
            for (int c = 0; c < 4; c++) acc[a][bq][c] = 0.f;

    const int KT = K >> 4;
    float4 ra[2];
    float  rb[8];

    auto ldg_tiles = [&](int kt) {
        #pragma unroll
        for (int l = 0; l < 2; l++) {
            int idx = tid + l * 256;
            int ar = idx >> 2, ak = (idx & 3) << 2;
            ra[l] = *reinterpret_cast<const float4*>(
                A + (size_t)(m0 + ar) * SEQ + (kt * 16 + ak));
        }
        #pragma unroll
        for (int l = 0; l < 8; l++) {
            int idx = tid + l * 256;
            rb[l] = B[(size_t)(kt * 16 + (idx >> 7)) * SEQ + n0 + (idx & 127)];
        }
    };
    auto sts_tiles = [&](int buf) {
        #pragma unroll
        for (int l = 0; l < 2; l++) {
            int idx = tid + l * 256;
            int ar = idx >> 2, ak = (idx & 3) << 2;
            As[buf][ar][ak + 0] = __uint_as_float(f2tf32(ra[l].x));
            As[buf][ar][ak + 1] = __uint_as_float(f2tf32(ra[l].y));
            As[buf][ar][ak + 2] = __uint_as_float(f2tf32(ra[l].z));
            As[buf][ar][ak + 3] = __uint_as_float(f2tf32(ra[l].w));
        }
        #pragma unroll
        for (int l = 0; l < 8; l++) {
            int idx = tid + l * 256;
            Bs[buf][idx >> 7][idx & 127] = __uint_as_float(f2tf32(rb[l]));
        }
    };
    auto compute = [&](int buf) {
        #pragma unroll
        for (int ks = 0; ks < 2; ks++) {
            uint32_t af[4][4];
            int k = ks * 8 + t4;
            #pragma unroll
            for (int tm = 0; tm < 4; tm++) {
                int r = wm + tm * 16 + g;
                af[tm][0] = __float_as_uint(As[buf][r][k]);
                af[tm][1] = __float_as_uint(As[buf][r + 8][k]);
                af[tm][2] = __float_as_uint(As[buf][r][k + 4]);
                af[tm][3] = __float_as_uint(As[buf][r + 8][k + 4]);
            }
            uint32_t bf[4][2];
            #pragma unroll
            for (int tn = 0; tn < 4; tn++) {
                int c = wn + tn * 8 + g;
                bf[tn][0] = __float_as_uint(Bs[buf][k][c]);
                bf[tn][1] = __float_as_uint(Bs[buf][k + 4][c]);
            }
            #pragma unroll
            for (int tm = 0; tm < 4; tm++)
                #pragma unroll
                for (int tn = 0; tn < 4; tn++)
                    asm volatile(
                        "mma.sync.aligned.m16n8k8.row.col.f32.tf32.tf32.f32 "
                        "{%0,%1,%2,%3}, {%4,%5,%6,%7}, {%8,%9}, {%0,%1,%2,%3};\n"
                        : "+f"(acc[tm][tn][0]), "+f"(acc[tm][tn][1]),
                          "+f"(acc[tm][tn][2]), "+f"(acc[tm][tn][3])
                        : "r"(af[tm][0]), "r"(af[tm][1]),
                          "r"(af[tm][2]), "r"(af[tm][3]),
                          "r"(bf[tn][0]), "r"(bf[tn][1]));
        }
    };

    ldg_tiles(0);
    sts_tiles(0);
    __syncthreads();
    for (int kt = 0; kt < KT; kt++) {
        if (kt + 1 < KT) ldg_tiles(kt + 1);
        compute(kt & 1);
        if (kt + 1 < KT) sts_tiles((kt + 1) & 1);
        __syncthreads();
    }

    #pragma unroll
    for (int tm = 0; tm < 4; tm++) {
        int r = m0 + wm + tm * 16 + g;
        #pragma unroll
        for (int tn = 0; tn < 4; tn++) {
            int c = n0 + wn + tn * 8 + (t4 << 1);
            C[(size_t)r * SEQ + c]           = acc[tm][tn][0];
            C[(size_t)r * SEQ + c + 1]       = acc[tm][tn][1];
            C[(size_t)(r + 8) * SEQ + c]     = acc[tm][tn][2];
            C[(size_t)(r + 8) * SEQ + c + 1] = acc[tm][tn][3];
        }
    }
}

__global__ __launch_bounds__(256, 2) void gemm_tf32_kernel(
    const float* __restrict__ A, const float* __restrict__ B,
    float* __restrict__ C, int K, long strideM)
{
    gemm_tf32_body(A + blockIdx.z * strideM, B + blockIdx.z * strideM,
                   C + blockIdx.z * strideM, blockIdx.x * 128, blockIdx.y * 128, K);
}

// dual: z in [0,8): z<4 -> C0 = A*B0 (batch z); z>=4 -> C1 = A*B1 (batch z-4)
__global__ __launch_bounds__(256, 2) void gemm_tf32_dual(
    const float* __restrict__ A,
    const float* __restrict__ B0, const float* __restrict__ B1,
    float* __restrict__ C0, float* __restrict__ C1,
    int K, long strideM)
{
    int z = blockIdx.z;
    int bz = z & 3;
    const float* B = (z < 4) ? B0 : B1;
    float*       C = (z < 4) ? C0 : C1;
    gemm_tf32_body(A + bz * strideM, B + bz * strideM, C + bz * strideM,
                   blockIdx.x * 128, blockIdx.y * 128, K);
}

// ================= final GEMM: fp16 mma + bulk pipeline, mbarrier flow =================
#define STG_BYTES (ACH * 2 + BCH * 2)   // 49152
#define NSTAGE 4
#define FSMEM (NSTAGE * STG_BYTES + 1024)

__global__ __launch_bounds__(256, 1) void gemm_final_fp16(
    const __half* __restrict__ A, const __half* __restrict__ B,
    float* __restrict__ C, const float* __restrict__ bias)
{
    extern __shared__ char dynsm[];
    __shared__ __align__(8) uint64_t s_full[NSTAGE];
    __shared__ __align__(8) uint64_t s_empty[NSTAGE];

    const int mt = blockIdx.x;
    const int nt = blockIdx.y;
    const int m0 = mt * 128;
    const int n0 = nt * 256;
    const int tid = threadIdx.x;
    const int lane = tid & 31, warp = tid >> 5;
    const int wm = (warp >> 2) * 64;
    const int wn = (warp & 3) * 64;
    const int g = lane >> 2, t4 = lane & 3;

    uint32_t raw_u = smem_u32(dynsm);
    uint32_t base_u = (raw_u + 1023u) & ~1023u;
    char* base_g = dynsm + (base_u - raw_u);

    const __half* Ach = A + (size_t)mt * KCHUNKS * ACH;
    const __half* Bch = B + (size_t)nt * KCHUNKS * BCH;

    uint32_t fullb[NSTAGE], emptyb[NSTAGE];
    #pragma unroll
    for (int s = 0; s < NSTAGE; s++) {
        fullb[s]  = smem_u32(&s_full[s]);
        emptyb[s] = smem_u32(&s_empty[s]);
    }

    if (tid == 0) {
        #pragma unroll
        for (int s = 0; s < NSTAGE; s++) {
            mbar_init(fullb[s], 1);
            mbar_init(emptyb[s], 8);
        }
    }
    __syncthreads();

    if (tid == 0) {
        #pragma unroll
        for (int s = 0; s < NSTAGE; s++) {
            mbar_expect_tx(fullb[s], STG_BYTES);
            bulk_g2s(base_u + s * STG_BYTES,           Ach + (size_t)s * ACH, ACH * 2, fullb[s]);
            bulk_g2s(base_u + s * STG_BYTES + ACH * 2, Bch + (size_t)s * BCH, BCH * 2, fullb[s]);
        }
    }

    float acc[4][8][4];
    #pragma unroll
    for (int a = 0; a < 4; a++)
        #pragma unroll
        for (int b = 0; b < 8; b++)
            #pragma unroll
            for (int c = 0; c < 4; c++) acc[a][b][c] = 0.f;

    int fph[NSTAGE] = {0, 0, 0, 0};
    int eph[NSTAGE] = {0, 0, 0, 0};

    for (int kc = 0; kc < KCHUNKS; kc++) {
        int s = kc & 3;   // NSTAGE == 4
        mbar_wait(fullb[s], fph[s]);
        fph[s] ^= 1;

        const char* a0 = base_g + s * STG_BYTES;
        const char* b0 = a0 + ACH * 2;

        #pragma unroll
        for (int kk = 0; kk < 4; kk++) {
            int kh = kk * 16 + 2 * t4;
            uint32_t af[4][4];
            #pragma unroll
            for (int tm = 0; tm < 4; tm++) {
                int r = wm + tm * 16 + g;
                af[tm][0] = *(const uint32_t*)(a0 + swz_half(r,     kh)     * 2);
                af[tm][1] = *(const uint32_t*)(a0 + swz_half(r + 8, kh)     * 2);
                af[tm][2] = *(const uint32_t*)(a0 + swz_half(r,     kh + 8) * 2);
                af[tm][3] = *(const uint32_t*)(a0 + swz_half(r + 8, kh + 8) * 2);
            }
            uint32_t bf[8][2];
            #pragma unroll
            for (int tn = 0; tn < 8; tn++) {
                int c = wn + tn * 8 + g;
                bf[tn][0] = *(const uint32_t*)(b0 + swz_half(c, kh)     * 2);
                bf[tn][1] = *(const uint32_t*)(b0 + swz_half(c, kh + 8) * 2);
            }
            #pragma unroll
            for (int tm = 0; tm < 4; tm++)
                #pragma unroll
                for (int tn = 0; tn < 8; tn++)
                    asm volatile(
                        "mma.sync.aligned.m16n8k16.row.col.f32.f16.f16.f32 "
                        "{%0,%1,%2,%3}, {%4,%5,%6,%7}, {%8,%9}, {%0,%1,%2,%3};\n"
                        : "+f"(acc[tm][tn][0]), "+f"(acc[tm][tn][1]),
                          "+f"(acc[tm][tn][2]), "+f"(acc[tm][tn][3])
                        : "r"(af[tm][0]), "r"(af[tm][1]),
                          "r"(af[tm][2]), "r"(af[tm][3]),
                          "r"(bf[tn][0]), "r"(bf[tn][1]));
        }

        __syncwarp();
        if (lane == 0) mbar_arrive(emptyb[s]);   // this warp done with stage s

        if (tid == 0) {
            int nkc = kc + NSTAGE;
            if (nkc < KCHUNKS) {
                mbar_wait(emptyb[s], eph[s]);    // all 8 warps released stage s
                eph[s] ^= 1;
                mbar_expect_tx(fullb[s], STG_BYTES);
                bulk_g2s(base_u + s * STG_BYTES,           Ach + (size_t)nkc * ACH, ACH * 2, fullb[s]);
                bulk_g2s(base_u + s * STG_BYTES + ACH * 2, Bch + (size_t)nkc * BCH, BCH * 2, fullb[s]);
            }
        }
    }

    #pragma unroll
    for (int tm = 0; tm < 4; tm++) {
        int r = m0 + wm + tm * 16 + g;
        #pragma unroll
        for (int tn = 0; tn < 8; tn++) {
            int c = n0 + wn + tn * 8 + (t4 << 1);
            if (c < VOCAB) {
                float bv = bias[c];
                C[(size_t)r * VOCAB + c]       = acc[tm][tn][0] + bv;
                C[(size_t)(r + 8) * VOCAB + c] = acc[tm][tn][2] + bv;
            }
            if (c + 1 < VOCAB) {
                float bv = bias[c + 1];
                C[(size_t)r * VOCAB + c + 1]       = acc[tm][tn][1] + bv;
                C[(size_t)(r + 8) * VOCAB + c + 1] = acc[tm][tn][3] + bv;
            }
        }
    }
}

// ================= diag(M^k) k=1..16 =================
__global__ __launch_bounds__(128) void diag_pe_kernel(
    const float* __restrict__ M1, const float* __restrict__ M2,
    const float* __restrict__ M3, const float* __restrict__ M4,
    const float* __restrict__ M8, const float* __restrict__ M12,
    float* __restrict__ x)
{
    int row = blockIdx.x;
    int b = row >> 9, i = row & (SEQ - 1);
    int tid = threadIdx.x, lane = tid & 31, warp = tid >> 5;
    long base = (long)row * SEQ;
    long mbq  = (long)b * SEQ * SEQ;

    __shared__ float rws[4][SEQ];
    __shared__ float cls[3][SEQ];
    __shared__ float wred[10][4];

    for (int j = tid; j < SEQ; j += 128) {
        rws[0][j] = M1[base + j];
        rws[1][j] = M2[base + j];
        rws[2][j] = M3[base + j];
        rws[3][j] = M4[base + j];
        cls[0][j] = M4 [mbq + (long)j * SEQ + i];
        cls[1][j] = M8 [mbq + (long)j * SEQ + i];
        cls[2][j] = M12[mbq + (long)j * SEQ + i];
    }
    __syncthreads();

    float part[10];
    #pragma unroll
    for (int p = 0; p < 10; p++) part[p] = 0.f;
    for (int j = tid; j < SEQ; j += 128) {
        float a1 = rws[0][j], a2 = rws[1][j], a3 = rws[2][j], a4 = rws[3][j];
        float c4 = cls[0][j], c8 = cls[1][j], c12 = cls[2][j];
        part[0] += a1 * c4;   part[1] += a2 * c4;   part[2] += a3 * c4;
        part[3] += a1 * c8;   part[4] += a2 * c8;   part[5] += a3 * c8;
        part[6] += a1 * c12;  part[7] += a2 * c12;  part[8] += a3 * c12;
        part[9] += a4 * c12;
    }
    #pragma unroll
    for (int p = 0; p < 10; p++) {
        float v = part[p];
        #pragma unroll
        for (int off = 16; off > 0; off >>= 1) v += __shfl_down_sync(0xffffffffu, v, off);
        if (lane == 0) wred[p][warp] = v;
    }
    __syncthreads();

    long xb = (long)row * DCAT + DEMB;
    if (tid < 10) {
        const int slot[10] = {4, 5, 6, 8, 9, 10, 12, 13, 14, 15};
        x[xb + slot[tid]] = wred[tid][0] + wred[tid][1] + wred[tid][2] + wred[tid][3];
    }
    if (tid == 0) {
        x[xb + 0]  = rws[0][i];
        x[xb + 1]  = rws[1][i];
        x[xb + 2]  = rws[2][i];
        x[xb + 3]  = rws[3][i];
        x[xb + 7]  = cls[1][i];
        x[xb + 11] = cls[2][i];
    }
}

extern "C" void kernel_launch(void* const* d_in, const int* in_sizes, int n_in,
                              void* d_out, int out_size)
{
    const int*   code  = (const int*)d_in[0];
    const int*   pos   = (const int*)d_in[1];
    const void*  mask  = d_in[2];
    const float* table = (const float*)d_in[3];
    const float* W     = (const float*)d_in[4];
    const float* bias  = (const float*)d_in[5];
    float* out = (float*)d_out;

    float *pM1, *pM2, *pM3, *pM4, *pM8, *pM12, *px;
    __half *pxh, *pwt;
    cudaGetSymbolAddress((void**)&pM1,  g_M1);
    cudaGetSymbolAddress((void**)&pM2,  g_M2);
    cudaGetSymbolAddress((void**)&pM3,  g_M3);
    cudaGetSymbolAddress((void**)&pM4,  g_M4);
    cudaGetSymbolAddress((void**)&pM8,  g_M8);
    cudaGetSymbolAddress((void**)&pM12, g_M12);
    cudaGetSymbolAddress((void**)&px,   g_x);
    cudaGetSymbolAddress((void**)&pxh,  g_xh);
    cudaGetSymbolAddress((void**)&pwt,  g_wt);

    const long MS = (long)SEQ * SEQ;

    cudaFuncSetAttribute(gemm_final_fp16,
                         cudaFuncAttributeMaxDynamicSharedMemorySize, FSMEM);

    reset_flags_kernel<<<1, 1>>>();
    detect_mask_kernel<<<64, 256>>>((const uint4*)mask, in_sizes[2] / 16);

    dim3 gW(NPAD / 32, (KPAD + 31) / 32);
    convert_w_kernel<<<gW, 256>>>(W, pwt);

    embed_kernel<<<NROWS, 256>>>(code, pos, mask, table, px);
    build_m_kernel<<<NROWS, 128>>>(mask, pM1);

    dim3 gP(SEQ / 128, SEQ / 128, BATCH);
    dim3 gD(SEQ / 128, SEQ / 128, 2 * BATCH);
    gemm_tf32_kernel<<<gP, 256>>>(pM1, pM1, pM2, SEQ, MS);
    gemm_tf32_dual<<<gD, 256>>>(pM2, pM1, pM2, pM3, pM4, SEQ, MS);  // M3=M2*M1, M4=M2*M2
    gemm_tf32_kernel<<<gP, 256>>>(pM4, pM4, pM8,  SEQ, MS);
    gemm_tf32_kernel<<<gP, 256>>>(pM8, pM4, pM12, SEQ, MS);

    diag_pe_kernel<<<NROWS, 128>>>(pM1, pM2, pM3, pM4, pM8, pM12, px);

    convert_x_kernel<<<(NROWS * KPAD + 255) / 256, 256>>>(px, pxh);

    dim3 gF(NROWS / 128, NPAD / 256, 1);   // (16, 197)
    gemm_final_fp16<<<gF, 256, FSMEM>>>(pxh, pwt, out, bias);
}